// round 1
// baseline (speedup 1.0000x reference)
#include <cuda_runtime.h>
#include <math.h>

// Problem constants
#define CB  4
#define CT  1024
#define CD  1024
#define CH  16
#define CDH 64

// ---------------------------------------------------------------------------
// Device scratch (static globals; no runtime allocation)
// ---------------------------------------------------------------------------
__device__ float g_Q[CB * CH * CT * CDH];          // [b,h,t,d]   16 MB
__device__ float g_K[CB * CH * CT * CDH];          // [b,h,t,d]   16 MB
__device__ float g_V[CB * CT * CDH];               // [b,t,d]      1 MB
__device__ float g_P[67108864];                    // [b,h,q,k]  256 MB (4*16*1024*1024)
__device__ float g_C[CB * CT * CD];                // ctx [b,t,h*64+d] 16 MB

// ---------------------------------------------------------------------------
// Generic tiled SGEMM + bias.
//   C[M,N] = A[M,K] @ W[K,N] + bias[N]
// mode: 1 -> C = g_Q (head-split layout), 2 -> C = g_K (head-split),
//       3 -> C = g_V (row-major), 4 -> A = g_C, C = Cext (row-major),
//       0 -> plain A=Aext, C=Cext.
// Tiles: BM=BN=64, BK=16, 256 threads, 4x4 per thread.
// ---------------------------------------------------------------------------
__global__ void __launch_bounds__(256)
sgemm_bias(const float* __restrict__ Aext, const float* __restrict__ W,
           const float* __restrict__ bias, float* __restrict__ Cext,
           int M, int N, int K, int mode)
{
    __shared__ __align__(16) float As[16][68];   // stored transposed: As[k][m]
    __shared__ __align__(16) float Bs[16][64];   // Bs[k][n]

    const float* A = (mode == 4) ? g_C : Aext;
    float* C = (mode == 1) ? g_Q : (mode == 2) ? g_K : (mode == 3) ? g_V : Cext;
    const bool headsplit = (mode == 1) || (mode == 2);

    const int tid = threadIdx.x;
    const int tx = tid & 15, ty = tid >> 4;
    const int r0 = blockIdx.y * 64, c0 = blockIdx.x * 64;

    const int arow = tid >> 2;          // 0..63
    const int ak   = (tid & 3) << 2;    // 0,4,8,12
    const int brow = tid >> 4;          // 0..15
    const int bn   = (tid & 15) << 2;   // 0..60

    float acc[4][4];
#pragma unroll
    for (int i = 0; i < 4; i++)
#pragma unroll
        for (int j = 0; j < 4; j++) acc[i][j] = 0.0f;

    for (int k0 = 0; k0 < K; k0 += 16) {
        float4 av = *reinterpret_cast<const float4*>(&A[(size_t)(r0 + arow) * K + k0 + ak]);
        float4 bv = *reinterpret_cast<const float4*>(&W[(size_t)(k0 + brow) * N + c0 + bn]);
        As[ak + 0][arow] = av.x;
        As[ak + 1][arow] = av.y;
        As[ak + 2][arow] = av.z;
        As[ak + 3][arow] = av.w;
        *reinterpret_cast<float4*>(&Bs[brow][bn]) = bv;
        __syncthreads();

#pragma unroll
        for (int kk = 0; kk < 16; kk++) {
            float4 a4 = *reinterpret_cast<const float4*>(&As[kk][ty << 2]);
            float4 b4 = *reinterpret_cast<const float4*>(&Bs[kk][tx << 2]);
            float aa[4] = {a4.x, a4.y, a4.z, a4.w};
            float bb[4] = {b4.x, b4.y, b4.z, b4.w};
#pragma unroll
            for (int i = 0; i < 4; i++)
#pragma unroll
                for (int j = 0; j < 4; j++)
                    acc[i][j] = fmaf(aa[i], bb[j], acc[i][j]);
        }
        __syncthreads();
    }

    const int cbase = c0 + (tx << 2);
    float bsv[4];
#pragma unroll
    for (int j = 0; j < 4; j++) bsv[j] = bias[cbase + j];

    if (!headsplit) {
#pragma unroll
        for (int i = 0; i < 4; i++) {
            int r = r0 + (ty << 2) + i;
            float4 o;
            o.x = acc[i][0] + bsv[0];
            o.y = acc[i][1] + bsv[1];
            o.z = acc[i][2] + bsv[2];
            o.w = acc[i][3] + bsv[3];
            *reinterpret_cast<float4*>(&C[(size_t)r * N + cbase]) = o;
        }
    } else {
        // c = h*64 + d ; row r = b*T + t ; write to [b,h,t,d]
        const int h = c0 >> 6;           // TILE_N==64 so h constant per block
        const int dbase = tx << 2;
#pragma unroll
        for (int i = 0; i < 4; i++) {
            int r = r0 + (ty << 2) + i;
            int b = r >> 10, t = r & 1023;
            float4 o;
            o.x = acc[i][0] + bsv[0];
            o.y = acc[i][1] + bsv[1];
            o.z = acc[i][2] + bsv[2];
            o.w = acc[i][3] + bsv[3];
            *reinterpret_cast<float4*>(
                &C[(size_t)((b << 4) + h) * 65536 + t * 64 + dbase]) = o;
        }
    }
}

// ---------------------------------------------------------------------------
// Attention kernel: one block = one (b,h) pair x 32 query rows.
//   S = (Q*scale) K^T  -> softmax rows -> write P, ctx = P V
// Dynamic smem:
//   S    [32][1032]  (padded row to kill reduction-phase bank conflicts)
//   QsmT [64][36]    (d-major transposed Q tile, scale folded in)
//   KVsm [64][68]    (K chunk d-major, then V chunk k-major, reused)
// ---------------------------------------------------------------------------
#define QT    32
#define SROW  1032
#define SM_S  (QT * SROW)       // 33024
#define SM_Q  (64 * 36)         // 2304
#define SM_KV (64 * 68)         // 4352
#define ATT_SMEM_BYTES ((SM_S + SM_Q + SM_KV) * 4)   // 158720

__global__ void __launch_bounds__(256)
attention_kernel()
{
    extern __shared__ __align__(16) float sm[];
    float* S    = sm;
    float* QsmT = sm + SM_S;
    float* KVsm = QsmT + SM_Q;

    const int tid = threadIdx.x;
    const int bh  = blockIdx.y;            // b*16 + h
    const int b   = bh >> 4;
    const int h   = bh & 15;
    const int q0  = blockIdx.x * QT;

    const float* Qg = g_Q + (size_t)bh * 65536 + (size_t)q0 * 64;
    const float* Kg = g_K + (size_t)bh * 65536;
    const float* Vg = g_V + (size_t)b * 65536;
    float*       Pg = g_P + (size_t)bh * 1048576 + (size_t)q0 * 1024;

    // ---- load Q tile, transpose to d-major, fold in 1/sqrt(DH) ----
    for (int v = tid; v < QT * 16; v += 256) {       // 512 float4 loads
        int row = v >> 4, c4 = (v & 15) << 2;
        float4 x = *reinterpret_cast<const float4*>(&Qg[row * 64 + c4]);
        QsmT[(c4 + 0) * 36 + row] = x.x * 0.125f;
        QsmT[(c4 + 1) * 36 + row] = x.y * 0.125f;
        QsmT[(c4 + 2) * 36 + row] = x.z * 0.125f;
        QsmT[(c4 + 3) * 36 + row] = x.w * 0.125f;
    }

    // ---- phase 1: S = Q K^T over 16 chunks of 64 keys ----
    const int qg = tid >> 5;   // 0..7   (4 q-rows each)
    const int kg = tid & 31;   // 0..31  (2 k-cols each)
    for (int kt = 0; kt < 16; kt++) {
        __syncthreads();
        // load 64 K rows, transposed to d-major
        for (int v = tid; v < 64 * 16; v += 256) {
            int row = v >> 4, c4 = (v & 15) << 2;
            float4 x = *reinterpret_cast<const float4*>(&Kg[(kt * 64 + row) * 64 + c4]);
            KVsm[(c4 + 0) * 68 + row] = x.x;
            KVsm[(c4 + 1) * 68 + row] = x.y;
            KVsm[(c4 + 2) * 68 + row] = x.z;
            KVsm[(c4 + 3) * 68 + row] = x.w;
        }
        __syncthreads();

        float acc[4][2];
#pragma unroll
        for (int i = 0; i < 4; i++) { acc[i][0] = 0.0f; acc[i][1] = 0.0f; }

#pragma unroll 16
        for (int d = 0; d < 64; d++) {
            float4 a  = *reinterpret_cast<const float4*>(&QsmT[d * 36 + (qg << 2)]);
            float2 kv = *reinterpret_cast<const float2*>(&KVsm[d * 68 + (kg << 1)]);
            acc[0][0] = fmaf(a.x, kv.x, acc[0][0]);
            acc[0][1] = fmaf(a.x, kv.y, acc[0][1]);
            acc[1][0] = fmaf(a.y, kv.x, acc[1][0]);
            acc[1][1] = fmaf(a.y, kv.y, acc[1][1]);
            acc[2][0] = fmaf(a.z, kv.x, acc[2][0]);
            acc[2][1] = fmaf(a.z, kv.y, acc[2][1]);
            acc[3][0] = fmaf(a.w, kv.x, acc[3][0]);
            acc[3][1] = fmaf(a.w, kv.y, acc[3][1]);
        }
        const int kc = kt * 64 + (kg << 1);
#pragma unroll
        for (int i = 0; i < 4; i++) {
            S[(qg * 4 + i) * SROW + kc]     = acc[i][0];
            S[(qg * 4 + i) * SROW + kc + 1] = acc[i][1];
        }
    }
    __syncthreads();

    // ---- phase 2: softmax each of 32 rows (warp per row), write P ----
    {
        const int warp = tid >> 5, lane = tid & 31;
        for (int r = warp; r < QT; r += 8) {
            float* row = S + r * SROW;
            float m = -1e30f;
            for (int c = lane; c < 1024; c += 32) m = fmaxf(m, row[c]);
#pragma unroll
            for (int o = 16; o; o >>= 1) m = fmaxf(m, __shfl_xor_sync(0xffffffffu, m, o));
            float s = 0.0f;
            for (int c = lane; c < 1024; c += 32) {
                float e = __expf(row[c] - m);
                row[c] = e;
                s += e;
            }
#pragma unroll
            for (int o = 16; o; o >>= 1) s += __shfl_xor_sync(0xffffffffu, s, o);
            float inv = 1.0f / s;
            for (int c = lane; c < 1024; c += 32) {
                float p = row[c] * inv;
                row[c] = p;
                Pg[r * 1024 + c] = p;
            }
        }
    }

    // ---- phase 3: ctx = P @ V, write [b,t,h*64+d] ----
    const int qi = tid >> 3;   // 0..31
    const int dg = tid & 7;    // 0..7 -> d = dg*8 .. +7
    float o[8];
#pragma unroll
    for (int j = 0; j < 8; j++) o[j] = 0.0f;

    for (int kt = 0; kt < 16; kt++) {
        __syncthreads();
        // load 64 V rows, k-major (no transpose)
        for (int v = tid; v < 64 * 16; v += 256) {
            int row = v >> 4, c4 = (v & 15) << 2;
            float4 x = *reinterpret_cast<const float4*>(&Vg[(kt * 64 + row) * 64 + c4]);
            *reinterpret_cast<float4*>(&KVsm[row * 68 + c4]) = x;
        }
        __syncthreads();

        const float* srow = &S[qi * SROW + kt * 64];
#pragma unroll 8
        for (int k = 0; k < 64; k++) {
            float s = srow[k];
            const float* vp = &KVsm[k * 68 + (dg << 3)];
            float4 v0 = *reinterpret_cast<const float4*>(vp);
            float4 v1 = *reinterpret_cast<const float4*>(vp + 4);
            o[0] = fmaf(s, v0.x, o[0]);
            o[1] = fmaf(s, v0.y, o[1]);
            o[2] = fmaf(s, v0.z, o[2]);
            o[3] = fmaf(s, v0.w, o[3]);
            o[4] = fmaf(s, v1.x, o[4]);
            o[5] = fmaf(s, v1.y, o[5]);
            o[6] = fmaf(s, v1.z, o[6]);
            o[7] = fmaf(s, v1.w, o[7]);
        }
    }

    float* cptr = g_C + (size_t)(b * 1024 + q0 + qi) * 1024 + h * 64 + (dg << 3);
    *reinterpret_cast<float4*>(cptr)     = make_float4(o[0], o[1], o[2], o[3]);
    *reinterpret_cast<float4*>(cptr + 4) = make_float4(o[4], o[5], o[6], o[7]);
}

// ---------------------------------------------------------------------------
// attn_mean[b,q,k] = (1/H) * sum_h P[b,h,q,k]
// ---------------------------------------------------------------------------
__global__ void __launch_bounds__(256)
attn_mean_kernel(float* __restrict__ outAttn)
{
    int idx = blockIdx.x * 256 + threadIdx.x;   // 0 .. 1048575 (float4 index)
    int e0 = idx << 2;
    int b = e0 >> 20;                           // T*T = 2^20
    int rem = e0 & 1048575;
    const float* base = g_P + ((size_t)b << 24) + rem;
    float4 acc = make_float4(0.f, 0.f, 0.f, 0.f);
#pragma unroll
    for (int h = 0; h < 16; h++) {
        float4 p = *reinterpret_cast<const float4*>(base + ((size_t)h << 20));
        acc.x += p.x; acc.y += p.y; acc.z += p.z; acc.w += p.w;
    }
    const float s = 1.0f / 16.0f;
    *reinterpret_cast<float4*>(&outAttn[e0]) =
        make_float4(acc.x * s, acc.y * s, acc.z * s, acc.w * s);
}

// ---------------------------------------------------------------------------
// kernel_launch
// Inputs (metadata order): x, Wq, bq, Wk, bk, Wv, bv, Wo, bo
// Output: out [B,T,D] (4194304 floats) then attn_mean [B,T,T] (4194304 floats)
// ---------------------------------------------------------------------------
extern "C" void kernel_launch(void* const* d_in, const int* in_sizes, int n_in,
                              void* d_out, int out_size)
{
    (void)in_sizes; (void)n_in; (void)out_size;
    const float* x  = (const float*)d_in[0];
    const float* Wq = (const float*)d_in[1];
    const float* bq = (const float*)d_in[2];
    const float* Wk = (const float*)d_in[3];
    const float* bk = (const float*)d_in[4];
    const float* Wv = (const float*)d_in[5];
    const float* bv = (const float*)d_in[6];
    const float* Wo = (const float*)d_in[7];
    const float* bo = (const float*)d_in[8];

    float* out     = (float*)d_out;
    float* outAttn = out + (size_t)CB * CT * CD;

    // Sticky attribute; first (uncaptured) correctness call sets it.
    cudaFuncSetAttribute(attention_kernel,
                         cudaFuncAttributeMaxDynamicSharedMemorySize,
                         ATT_SMEM_BYTES);

    dim3 blk(256);
    // Q = x@Wq + bq  -> g_Q [b,h,t,d]
    sgemm_bias<<<dim3(16, 64), blk>>>(x, Wq, bq, nullptr, 4096, 1024, 1024, 1);
    // K = x@Wk + bk  -> g_K [b,h,t,d]
    sgemm_bias<<<dim3(16, 64), blk>>>(x, Wk, bk, nullptr, 4096, 1024, 1024, 2);
    // V = x@Wv + bv  -> g_V [b,t,d]
    sgemm_bias<<<dim3(1, 64), blk>>>(x, Wv, bv, nullptr, 4096, 64, 1024, 3);
    // attention: P (scratch) + ctx -> g_C
    attention_kernel<<<dim3(32, 64), blk, ATT_SMEM_BYTES>>>();
    // attn_mean -> second half of d_out
    attn_mean_kernel<<<4096, blk>>>(outAttn);
    // out = ctx @ Wo + bo -> first half of d_out
    sgemm_bias<<<dim3(16, 64), blk>>>(nullptr, Wo, bo, out, 4096, 1024, 1024, 4);
}

// round 3
// speedup vs baseline: 3.6096x; 3.6096x over previous
#include <cuda_runtime.h>
#include <cuda_bf16.h>
#include <cstdint>
#include <cstddef>

// Problem constants: B=4, T=1024, D=1024, H=16, DH=64
#define MB ((size_t)1 << 20)

// ---------------------------------------------------------------------------
// Static device heap (no runtime allocation). Offsets in bytes.
// ---------------------------------------------------------------------------
#define OFF_XHI   (0 * MB)
#define OFF_XLO   (8 * MB)
#define OFF_WQTHI (16 * MB)
#define OFF_WQTLO (18 * MB)
#define OFF_WKTHI (20 * MB)
#define OFF_WKTLO (22 * MB)
#define OFF_WOTHI (24 * MB)
#define OFF_WOTLO (26 * MB)
#define OFF_WVTHI (28 * MB)
#define OFF_WVTLO (28 * MB + 131072)
#define OFF_QHI   (29 * MB)
#define OFF_QLO   (37 * MB)
#define OFF_KHI   (45 * MB)
#define OFF_KLO   (53 * MB)
#define OFF_VTHI  (61 * MB)
#define OFF_VTLO  (61 * MB + 524288)
#define OFF_CHI   (62 * MB)
#define OFF_CLO   (70 * MB)
#define OFF_S     (78 * MB)          // raw scores fp32 [bh,q,k]  256 MB
#define OFF_PHI   (334 * MB)         // probs bf16 hi             128 MB
#define OFF_PLO   (462 * MB)
#define HEAP_BYTES (590 * MB)

__device__ char g_heap[HEAP_BYTES];

// ---------------------------------------------------------------------------
// PTX helpers (Ampere-compatible: ldmatrix / mma.sync / cp.async)
// ---------------------------------------------------------------------------
__device__ __forceinline__ uint32_t smem_u32(const void* p) {
    uint32_t a;
    asm("{ .reg .u64 t; cvta.to.shared.u64 t, %1; cvt.u32.u64 %0, t; }" : "=r"(a) : "l"(p));
    return a;
}
__device__ __forceinline__ void ldm_x4(uint32_t* r, uint32_t addr) {
    asm volatile("ldmatrix.sync.aligned.m8n8.x4.shared.b16 {%0,%1,%2,%3}, [%4];"
                 : "=r"(r[0]), "=r"(r[1]), "=r"(r[2]), "=r"(r[3]) : "r"(addr));
}
__device__ __forceinline__ void mma16816(float* c, const uint32_t* a,
                                         uint32_t b0, uint32_t b1) {
    asm volatile(
        "mma.sync.aligned.m16n8k16.row.col.f32.bf16.bf16.f32 "
        "{%0,%1,%2,%3}, {%4,%5,%6,%7}, {%8,%9}, {%0,%1,%2,%3};"
        : "+f"(c[0]), "+f"(c[1]), "+f"(c[2]), "+f"(c[3])
        : "r"(a[0]), "r"(a[1]), "r"(a[2]), "r"(a[3]), "r"(b0), "r"(b1));
}
__device__ __forceinline__ void cpa16(uint32_t saddr, const void* g) {
    asm volatile("cp.async.cg.shared.global [%0], [%1], 16;" :: "r"(saddr), "l"(g));
}
#define CP_COMMIT() asm volatile("cp.async.commit_group;" ::: "memory")
#define CP_WAIT(N)  asm volatile("cp.async.wait_group %0;" :: "n"(N) : "memory")

// bf16 split helpers ---------------------------------------------------------
__device__ __forceinline__ void split_bf16(float v, unsigned short& h, unsigned short& l) {
    __nv_bfloat16 bh = __float2bfloat16(v);
    float r = v - __bfloat162float(bh);
    h = __bfloat16_as_ushort(bh);
    l = __bfloat16_as_ushort(__float2bfloat16(r));
}
__device__ __forceinline__ uint32_t pack2u(unsigned short a, unsigned short b) {
    return (uint32_t)a | ((uint32_t)b << 16);
}
__device__ __forceinline__ uint2 pack4u(unsigned short a, unsigned short b,
                                        unsigned short c, unsigned short d) {
    return make_uint2(pack2u(a, b), pack2u(c, d));
}
__device__ __forceinline__ float bf_lo(uint32_t u) {
    return __bfloat162float(__ushort_as_bfloat16((unsigned short)(u & 0xffff)));
}
__device__ __forceinline__ float bf_hi(uint32_t u) {
    return __bfloat162float(__ushort_as_bfloat16((unsigned short)(u >> 16)));
}

// ---------------------------------------------------------------------------
// Conversion kernels
// ---------------------------------------------------------------------------
__global__ void __launch_bounds__(256)
conv_split(const float* __restrict__ x, __nv_bfloat16* __restrict__ hi,
           __nv_bfloat16* __restrict__ lo, int n4)
{
    int i = blockIdx.x * 256 + threadIdx.x;
    if (i >= n4) return;
    float4 v = reinterpret_cast<const float4*>(x)[i];
    unsigned short h0, h1, h2, h3, l0, l1, l2, l3;
    split_bf16(v.x, h0, l0); split_bf16(v.y, h1, l1);
    split_bf16(v.z, h2, l2); split_bf16(v.w, h3, l3);
    reinterpret_cast<uint2*>(hi)[i] = pack4u(h0, h1, h2, h3);
    reinterpret_cast<uint2*>(lo)[i] = pack4u(l0, l1, l2, l3);
}

// W [K,N] row-major -> W^T hi/lo bf16 [N,K]
__global__ void __launch_bounds__(256)
convT_split(const float* __restrict__ W, __nv_bfloat16* __restrict__ Thi,
            __nv_bfloat16* __restrict__ Tlo, int K, int N)
{
    __shared__ float sm[32][33];
    int n0 = blockIdx.x * 32, k0 = blockIdx.y * 32;
    int tx = threadIdx.x, ty = threadIdx.y;       // (32, 8)
#pragma unroll
    for (int i = 0; i < 32; i += 8)
        sm[ty + i][tx] = W[(size_t)(k0 + ty + i) * N + n0 + tx];
    __syncthreads();
#pragma unroll
    for (int i = 0; i < 32; i += 8) {
        float v = sm[tx][ty + i];
        unsigned short h, l;
        split_bf16(v, h, l);
        size_t o = (size_t)(n0 + ty + i) * K + k0 + tx;
        Thi[o] = __ushort_as_bfloat16(h);
        Tlo[o] = __ushort_as_bfloat16(l);
    }
}

// ---------------------------------------------------------------------------
// bf16x3 GEMM via mma.sync (HMMA):  D[m,n] = sum_k A[m,k]*B[n,k]
// Block 128x64x32, 256 threads, 8 warps (4M x 2N), warp tile 32x32.
// Epilogue modes:
//   0: fp32 row-major (+bias,*scale):  outF + z*outBS + row*ldOut + col
//   1: head-split bf16 hi/lo (+bias,*scale):  [b,h,t,d]
//   2: V^T bf16 hi/lo (+bias):  [b, col, t]
//   3: ctx bf16 hi/lo:  [(b*1024+row)*1024 + h*64 + col], z = b*16+h
// ---------------------------------------------------------------------------
#define APAD_STRIDE 80          // 32 bf16 = 64B payload, padded to 80B
#define A_TERM (128 * APAD_STRIDE)   // 10240
#define B_TERM (64 * APAD_STRIDE)    // 5120
#define BUF_BYTES (2 * A_TERM + 2 * B_TERM)   // 30720
#define GEMM_SMEM (2 * BUF_BYTES)             // 61440

__global__ void __launch_bounds__(256)
gemm_bf16x3(const __nv_bfloat16* __restrict__ Ahi, const __nv_bfloat16* __restrict__ Alo,
            size_t aBS, int lda,
            const __nv_bfloat16* __restrict__ Bhi, const __nv_bfloat16* __restrict__ Blo,
            size_t bBS, int bDiv, int ldb,
            int K,
            const float* __restrict__ bias, float scale,
            float* __restrict__ outF, size_t outBS, int ldOut,
            __nv_bfloat16* __restrict__ outHi, __nv_bfloat16* __restrict__ outLo,
            int mode)
{
    extern __shared__ __align__(16) char smem[];
    const uint32_t sbase = smem_u32(smem);
    const int tid  = threadIdx.x;
    const int lane = tid & 31;
    const int wid  = tid >> 5;
    const int wm   = wid & 3;       // 0..3  (M)
    const int wn   = wid >> 2;      // 0..1  (N)
    const int m0   = blockIdx.y * 128;
    const int n0   = blockIdx.x * 64;
    const int z    = blockIdx.z;

    const __nv_bfloat16* Ah = Ahi + (size_t)z * aBS;
    const __nv_bfloat16* Al = Alo + (size_t)z * aBS;
    const __nv_bfloat16* Bh = Bhi + (size_t)(z / bDiv) * bBS;
    const __nv_bfloat16* Bl = Blo + (size_t)(z / bDiv) * bBS;

    // staging indices
    const int aRow = tid >> 2;           // 0..63 (plus +64 on second pass)
    const int slot = tid & 3;            // 16B slot within 64B row payload
    const int bRow = tid >> 2;           // 0..63

    // ldmatrix per-lane offsets (within a term region)
    const uint32_t aLdmOff = (uint32_t)((wm * 32 + (lane & 15)) * APAD_STRIDE + (lane >> 4) * 16);
    const uint32_t bLdmOff = (uint32_t)((wn * 32 + (lane & 15)) * APAD_STRIDE + (lane >> 4) * 16);

    float acc[2][2][2][4];
#pragma unroll
    for (int i = 0; i < 2; i++)
#pragma unroll
        for (int j = 0; j < 2; j++)
#pragma unroll
            for (int k = 0; k < 2; k++)
#pragma unroll
                for (int l = 0; l < 4; l++) acc[i][j][k][l] = 0.0f;

    const int nc = K >> 5;   // chunks of 32

    // ---- stage chunk 0 ----
    {
        const int k0 = 0;
#pragma unroll
        for (int p = 0; p < 2; p++) {
            int row = aRow + p * 64;
            size_t go = (size_t)(m0 + row) * lda + k0 + slot * 8;
            uint32_t so = sbase + (uint32_t)(row * APAD_STRIDE + slot * 16);
            cpa16(so, Ah + go);
            cpa16(so + A_TERM, Al + go);
        }
        size_t go = (size_t)(n0 + bRow) * ldb + k0 + slot * 8;
        uint32_t so = sbase + 2 * A_TERM + (uint32_t)(bRow * APAD_STRIDE + slot * 16);
        cpa16(so, Bh + go);
        cpa16(so + B_TERM, Bl + go);
        CP_COMMIT();
    }

    for (int c = 0; c < nc; c++) {
        if (c + 1 < nc) {
            const int k0 = (c + 1) << 5;
            const uint32_t bbuf = sbase + ((c + 1) & 1) * BUF_BYTES;
#pragma unroll
            for (int p = 0; p < 2; p++) {
                int row = aRow + p * 64;
                size_t go = (size_t)(m0 + row) * lda + k0 + slot * 8;
                uint32_t so = bbuf + (uint32_t)(row * APAD_STRIDE + slot * 16);
                cpa16(so, Ah + go);
                cpa16(so + A_TERM, Al + go);
            }
            size_t go = (size_t)(n0 + bRow) * ldb + k0 + slot * 8;
            uint32_t so = bbuf + 2 * A_TERM + (uint32_t)(bRow * APAD_STRIDE + slot * 16);
            cpa16(so, Bh + go);
            cpa16(so + B_TERM, Bl + go);
            CP_COMMIT();
            CP_WAIT(1);
        } else {
            CP_WAIT(0);
        }
        __syncthreads();

        const uint32_t cbuf = sbase + (c & 1) * BUF_BYTES;
        const uint32_t aHiB = cbuf + aLdmOff;
        const uint32_t aLoB = cbuf + A_TERM + aLdmOff;
        const uint32_t bHiB = cbuf + 2 * A_TERM + bLdmOff;
        const uint32_t bLoB = cbuf + 2 * A_TERM + B_TERM + bLdmOff;

#pragma unroll
        for (int ks = 0; ks < 2; ks++) {
            const uint32_t ko = ks * 32;   // 16 bf16 = 32 bytes
            uint32_t ahi[2][4], alo[2][4], bhi[2][4], blo[2][4];
            ldm_x4(ahi[0], aHiB + ko);
            ldm_x4(ahi[1], aHiB + ko + 16 * APAD_STRIDE);
            ldm_x4(alo[0], aLoB + ko);
            ldm_x4(alo[1], aLoB + ko + 16 * APAD_STRIDE);
            ldm_x4(bhi[0], bHiB + ko);
            ldm_x4(bhi[1], bHiB + ko + 16 * APAD_STRIDE);
            ldm_x4(blo[0], bLoB + ko);
            ldm_x4(blo[1], bLoB + ko + 16 * APAD_STRIDE);

#pragma unroll
            for (int mt = 0; mt < 2; mt++)
#pragma unroll
                for (int nt = 0; nt < 2; nt++)
#pragma unroll
                    for (int nh = 0; nh < 2; nh++) {
                        float* cc = acc[mt][nt][nh];
                        mma16816(cc, ahi[mt], bhi[nt][nh], bhi[nt][nh + 2]);
                        mma16816(cc, ahi[mt], blo[nt][nh], blo[nt][nh + 2]);
                        mma16816(cc, alo[mt], bhi[nt][nh], bhi[nt][nh + 2]);
                    }
        }
        __syncthreads();
    }

    // ---- epilogue ----
    const int rr = lane >> 2;
    const int cc2 = (lane & 3) << 1;
#pragma unroll
    for (int mt = 0; mt < 2; mt++)
#pragma unroll
        for (int nt = 0; nt < 2; nt++)
#pragma unroll
            for (int nh = 0; nh < 2; nh++) {
                const float* cv = acc[mt][nt][nh];
                int gc = n0 + wn * 32 + nt * 16 + nh * 8 + cc2;
                float b0 = 0.f, b1 = 0.f;
                if (bias) { b0 = bias[gc]; b1 = bias[gc + 1]; }
#pragma unroll
                for (int half = 0; half < 2; half++) {
                    int gr = m0 + wm * 32 + mt * 16 + rr + half * 8;
                    float v0 = (cv[half * 2 + 0] + b0) * scale;
                    float v1 = (cv[half * 2 + 1] + b1) * scale;
                    if (mode == 0) {
                        float* p = outF + (size_t)z * outBS + (size_t)gr * ldOut + gc;
                        *reinterpret_cast<float2*>(p) = make_float2(v0, v1);
                    } else if (mode == 1) {
                        int bb = gr >> 10, t = gr & 1023;
                        int h = gc >> 6, d = gc & 63;
                        size_t idx = ((size_t)((bb << 4) + h) << 16) + ((size_t)t << 6) + d;
                        unsigned short h0, h1, l0, l1;
                        split_bf16(v0, h0, l0); split_bf16(v1, h1, l1);
                        *reinterpret_cast<uint32_t*>(outHi + idx) = pack2u(h0, h1);
                        *reinterpret_cast<uint32_t*>(outLo + idx) = pack2u(l0, l1);
                    } else if (mode == 2) {
                        int bb = gr >> 10, t = gr & 1023;
                        unsigned short h0, h1, l0, l1;
                        split_bf16(v0, h0, l0); split_bf16(v1, h1, l1);
                        size_t i0 = ((size_t)bb << 16) + ((size_t)gc << 10) + t;
                        outHi[i0] = __ushort_as_bfloat16(h0);
                        outLo[i0] = __ushort_as_bfloat16(l0);
                        outHi[i0 + 1024] = __ushort_as_bfloat16(h1);
                        outLo[i0 + 1024] = __ushort_as_bfloat16(l1);
                    } else {  // mode 3: ctx
                        int bb = z >> 4, h = z & 15;
                        size_t idx = (((size_t)(bb << 10) + gr) << 10) + (h << 6) + gc;
                        unsigned short h0, h1, l0, l1;
                        split_bf16(v0, h0, l0); split_bf16(v1, h1, l1);
                        *reinterpret_cast<uint32_t*>(outHi + idx) = pack2u(h0, h1);
                        *reinterpret_cast<uint32_t*>(outLo + idx) = pack2u(l0, l1);
                    }
                }
            }
}

// ---------------------------------------------------------------------------
// Softmax over 65536 rows of 1024: read S fp32, write P bf16 hi/lo.
// ---------------------------------------------------------------------------
__global__ void __launch_bounds__(256)
softmax_kernel(const float* __restrict__ S, __nv_bfloat16* __restrict__ Phi,
               __nv_bfloat16* __restrict__ Plo)
{
    const int row = blockIdx.x * 8 + (threadIdx.x >> 5);
    const int lane = threadIdx.x & 31;
    const float* sr = S + (size_t)row * 1024;

    float4 v[8];
    float m = -1e30f;
#pragma unroll
    for (int i = 0; i < 8; i++) {
        v[i] = *reinterpret_cast<const float4*>(sr + ((i * 32 + lane) << 2));
        m = fmaxf(m, fmaxf(fmaxf(v[i].x, v[i].y), fmaxf(v[i].z, v[i].w)));
    }
#pragma unroll
    for (int o = 16; o; o >>= 1) m = fmaxf(m, __shfl_xor_sync(0xffffffffu, m, o));

    float s = 0.0f;
#pragma unroll
    for (int i = 0; i < 8; i++) {
        v[i].x = __expf(v[i].x - m); v[i].y = __expf(v[i].y - m);
        v[i].z = __expf(v[i].z - m); v[i].w = __expf(v[i].w - m);
        s += (v[i].x + v[i].y) + (v[i].z + v[i].w);
    }
#pragma unroll
    for (int o = 16; o; o >>= 1) s += __shfl_xor_sync(0xffffffffu, s, o);
    const float inv = 1.0f / s;

#pragma unroll
    for (int i = 0; i < 8; i++) {
        size_t e = (size_t)row * 1024 + ((i * 32 + lane) << 2);
        unsigned short h0, h1, h2, h3, l0, l1, l2, l3;
        split_bf16(v[i].x * inv, h0, l0);
        split_bf16(v[i].y * inv, h1, l1);
        split_bf16(v[i].z * inv, h2, l2);
        split_bf16(v[i].w * inv, h3, l3);
        *reinterpret_cast<uint2*>(Phi + e) = pack4u(h0, h1, h2, h3);
        *reinterpret_cast<uint2*>(Plo + e) = pack4u(l0, l1, l2, l3);
    }
}

// ---------------------------------------------------------------------------
// attn_mean[b,q,k] = (1/16) * sum_h (Phi + Plo)
// ---------------------------------------------------------------------------
__global__ void __launch_bounds__(256)
attn_mean_kernel(const __nv_bfloat16* __restrict__ Phi,
                 const __nv_bfloat16* __restrict__ Plo, float* __restrict__ out)
{
    size_t idx = (size_t)blockIdx.x * 256 + threadIdx.x;
    size_t e0 = idx << 2;
    int b = (int)(e0 >> 20);
    size_t rem = e0 & 1048575;
    float a0 = 0.f, a1 = 0.f, a2 = 0.f, a3 = 0.f;
#pragma unroll
    for (int h = 0; h < 16; h++) {
        size_t base = (((size_t)(b * 16 + h)) << 20) + rem;
        uint2 uh = *reinterpret_cast<const uint2*>(Phi + base);
        uint2 ul = *reinterpret_cast<const uint2*>(Plo + base);
        a0 += bf_lo(uh.x) + bf_lo(ul.x);
        a1 += bf_hi(uh.x) + bf_hi(ul.x);
        a2 += bf_lo(uh.y) + bf_lo(ul.y);
        a3 += bf_hi(uh.y) + bf_hi(ul.y);
    }
    const float s = 1.0f / 16.0f;
    *reinterpret_cast<float4*>(out + e0) = make_float4(a0 * s, a1 * s, a2 * s, a3 * s);
}

// ---------------------------------------------------------------------------
// kernel_launch. Inputs: x, Wq, bq, Wk, bk, Wv, bv, Wo, bo
// Output: out [4,1024,1024] fp32 then attn_mean [4,1024,1024] fp32
// ---------------------------------------------------------------------------
extern "C" void kernel_launch(void* const* d_in, const int* in_sizes, int n_in,
                              void* d_out, int out_size)
{
    (void)in_sizes; (void)n_in; (void)out_size;
    const float* x  = (const float*)d_in[0];
    const float* Wq = (const float*)d_in[1];
    const float* bq = (const float*)d_in[2];
    const float* Wk = (const float*)d_in[3];
    const float* bk = (const float*)d_in[4];
    const float* Wv = (const float*)d_in[5];
    const float* bv = (const float*)d_in[6];
    const float* Wo = (const float*)d_in[7];
    const float* bo = (const float*)d_in[8];
    float* out     = (float*)d_out;
    float* outAttn = out + 4194304;

    char* hp = nullptr;
    cudaGetSymbolAddress((void**)&hp, g_heap);
    __nv_bfloat16* Xhi   = (__nv_bfloat16*)(hp + OFF_XHI);
    __nv_bfloat16* Xlo   = (__nv_bfloat16*)(hp + OFF_XLO);
    __nv_bfloat16* WqThi = (__nv_bfloat16*)(hp + OFF_WQTHI);
    __nv_bfloat16* WqTlo = (__nv_bfloat16*)(hp + OFF_WQTLO);
    __nv_bfloat16* WkThi = (__nv_bfloat16*)(hp + OFF_WKTHI);
    __nv_bfloat16* WkTlo = (__nv_bfloat16*)(hp + OFF_WKTLO);
    __nv_bfloat16* WoThi = (__nv_bfloat16*)(hp + OFF_WOTHI);
    __nv_bfloat16* WoTlo = (__nv_bfloat16*)(hp + OFF_WOTLO);
    __nv_bfloat16* WvThi = (__nv_bfloat16*)(hp + OFF_WVTHI);
    __nv_bfloat16* WvTlo = (__nv_bfloat16*)(hp + OFF_WVTLO);
    __nv_bfloat16* Qhi   = (__nv_bfloat16*)(hp + OFF_QHI);
    __nv_bfloat16* Qlo   = (__nv_bfloat16*)(hp + OFF_QLO);
    __nv_bfloat16* Khi   = (__nv_bfloat16*)(hp + OFF_KHI);
    __nv_bfloat16* Klo   = (__nv_bfloat16*)(hp + OFF_KLO);
    __nv_bfloat16* Vthi  = (__nv_bfloat16*)(hp + OFF_VTHI);
    __nv_bfloat16* Vtlo  = (__nv_bfloat16*)(hp + OFF_VTLO);
    __nv_bfloat16* Chi   = (__nv_bfloat16*)(hp + OFF_CHI);
    __nv_bfloat16* Clo   = (__nv_bfloat16*)(hp + OFF_CLO);
    __nv_bfloat16* Phi   = (__nv_bfloat16*)(hp + OFF_PHI);
    __nv_bfloat16* Plo   = (__nv_bfloat16*)(hp + OFF_PLO);
    float*         Sbuf  = (float*)(hp + OFF_S);

    cudaFuncSetAttribute(gemm_bf16x3, cudaFuncAttributeMaxDynamicSharedMemorySize, GEMM_SMEM);

    // conversions
    conv_split<<<4096, 256>>>(x, Xhi, Xlo, 1048576);
    convT_split<<<dim3(32, 32), dim3(32, 8)>>>(Wq, WqThi, WqTlo, 1024, 1024);
    convT_split<<<dim3(32, 32), dim3(32, 8)>>>(Wk, WkThi, WkTlo, 1024, 1024);
    convT_split<<<dim3(32, 32), dim3(32, 8)>>>(Wo, WoThi, WoTlo, 1024, 1024);
    convT_split<<<dim3(2, 32),  dim3(32, 8)>>>(Wv, WvThi, WvTlo, 1024, 64);

    // Q projection (scale 1/8 folded in) -> head-split bf16 hi/lo
    gemm_bf16x3<<<dim3(16, 32, 1), 256, GEMM_SMEM>>>(
        Xhi, Xlo, 0, 1024, WqThi, WqTlo, 0, 1, 1024, 1024,
        bq, 0.125f, nullptr, 0, 0, Qhi, Qlo, 1);
    // K projection -> head-split bf16 hi/lo
    gemm_bf16x3<<<dim3(16, 32, 1), 256, GEMM_SMEM>>>(
        Xhi, Xlo, 0, 1024, WkThi, WkTlo, 0, 1, 1024, 1024,
        bk, 1.0f, nullptr, 0, 0, Khi, Klo, 1);
    // V projection -> V^T [b,d,t] bf16 hi/lo
    gemm_bf16x3<<<dim3(1, 32, 1), 256, GEMM_SMEM>>>(
        Xhi, Xlo, 0, 1024, WvThi, WvTlo, 0, 1, 1024, 1024,
        bv, 1.0f, nullptr, 0, 0, Vthi, Vtlo, 2);
    // S = Q K^T (64 batches over b,h; K=64) -> fp32
    gemm_bf16x3<<<dim3(16, 8, 64), 256, GEMM_SMEM>>>(
        Qhi, Qlo, 65536, 64, Khi, Klo, 65536, 1, 64, 64,
        nullptr, 1.0f, Sbuf, 1048576, 1024, nullptr, nullptr, 0);
    // softmax -> P bf16 hi/lo
    softmax_kernel<<<8192, 256>>>(Sbuf, Phi, Plo);
    // ctx = P V (64 batches, V^T shared per b) -> ctx bf16 hi/lo
    gemm_bf16x3<<<dim3(1, 8, 64), 256, GEMM_SMEM>>>(
        Phi, Plo, 1048576, 1024, Vthi, Vtlo, 65536, 16, 1024, 1024,
        nullptr, 1.0f, nullptr, 0, 0, Chi, Clo, 3);
    // attn_mean
    attn_mean_kernel<<<4096, 256>>>(Phi, Plo, outAttn);
    // out = ctx @ Wo + bo -> fp32 d_out
    gemm_bf16x3<<<dim3(16, 32, 1), 256, GEMM_SMEM>>>(
        Chi, Clo, 0, 1024, WoThi, WoTlo, 0, 1, 1024, 1024,
        bo, 1.0f, out, 0, 1024, nullptr, nullptr, 0);
}